// round 15
// baseline (speedup 1.0000x reference)
#include <cuda_runtime.h>
#include <cuda_fp16.h>
#include <cstdint>

#define HCH  512
#define LSEQ 4096
#define TAPS 64

#define NT    256               // 8 warps
#define TCTA  512               // 4 seq-tiles of 128 per CTA
#define STRW  292               // u32 words per batch strip (288 used + 4 pad), 292%32==4
#define NTAB  11                // deduped A-frag words: fw0[0..4], fw1[0..5]

__device__ __forceinline__ uint32_t pk_h2(float a, float b) {
    __half2 t = __floats2half2_rn(a, b);
    return *reinterpret_cast<uint32_t*>(&t);
}
__device__ __forceinline__ uint32_t smem_u32(const void* p) {
    uint32_t a;
    asm("{ .reg .u64 t; cvta.to.shared.u64 t, %1; cvt.u32.u64 %0, t; }" : "=r"(a) : "l"(p));
    return a;
}
__device__ __forceinline__ void mma_f16(float* d, uint32_t a0, uint32_t a1,
                                        uint32_t a2, uint32_t a3,
                                        uint32_t b0, uint32_t b1) {
    asm volatile(
        "mma.sync.aligned.m16n8k16.row.col.f32.f16.f16.f32 "
        "{%0,%1,%2,%3}, {%4,%5,%6,%7}, {%8,%9}, {%0,%1,%2,%3};"
        : "+f"(d[0]), "+f"(d[1]), "+f"(d[2]), "+f"(d[3])
        : "r"(a0), "r"(a1), "r"(a2), "r"(a3), "r"(b0), "r"(b1));
}
__device__ __forceinline__ void ldsm_x4(uint32_t& r0, uint32_t& r1,
                                        uint32_t& r2, uint32_t& r3, uint32_t addr) {
    asm volatile("ldmatrix.sync.aligned.m8n8.x4.shared.b16 {%0,%1,%2,%3}, [%4];"
                 : "=r"(r0), "=r"(r1), "=r"(r2), "=r"(r3) : "r"(addr));
}

__global__ __launch_bounds__(NT, 6) void conv_mma(const float* __restrict__ up,
                                                  const float* __restrict__ Bp,
                                                  const float* __restrict__ Cp,
                                                  const float* __restrict__ Dp,
                                                  float* __restrict__ yp) {
    __shared__ alignas(16) uint32_t sBuf[8 * STRW];      // 8 fp16 batch strips
    __shared__ alignas(16) float sBC[192];               // B | C | zero pad
    __shared__ float    sK[TAPS];
    __shared__ uint32_t sTab[NTAB * 32];                 // deduped A-frag words

    const int tid  = threadIdx.x;
    const int wid  = tid >> 5;
    const int lane = tid & 31;
    const int h    = blockIdx.y;
    const int t0   = blockIdx.x * TCTA;

    const float* uh = up + (size_t)h * LSEQ;
    float*       yh = yp + (size_t)h * LSEQ;
    const size_t bstr = (size_t)HCH * LSEQ;

    if (tid < 64) {
        // ---- warps 0-1: stage B,C (+zero pad); K correlation; A-frag table ----
        float dval = 0.0f;
        if (tid == 0) dval = Dp[h];
        if (tid < 32) {
            int l = tid & 15;
            const float* src = (tid < 16) ? (Bp + h * TAPS) : (Cp + h * TAPS);
            reinterpret_cast<float4*>(sBC)[(tid < 16 ? 0 : 16) + l] =
                reinterpret_cast<const float4*>(src)[l];
        } else if (tid < 48) {                           // zero pad sBC[128..191]
            reinterpret_cast<float4*>(sBC)[tid] = make_float4(0.f, 0.f, 0.f, 0.f);
        }
        asm volatile("bar.sync 1, 64;" ::: "memory");

        {   // K[s] = sum_j B[j]*C[j+s] (branch-free via pad), K[0] += D[h]
            const int s = tid;
            float a0 = 0.f, a1 = 0.f, a2 = 0.f, a3 = 0.f;
            #pragma unroll
            for (int j = 0; j < TAPS; j += 4) {
                a0 = fmaf(sBC[j],     sBC[64 + j + s],     a0);
                a1 = fmaf(sBC[j + 1], sBC[64 + j + 1 + s], a1);
                a2 = fmaf(sBC[j + 2], sBC[64 + j + 2 + s], a2);
                a3 = fmaf(sBC[j + 3], sBC[64 + j + 3 + s], a3);
            }
            sK[s] = (a0 + a1) + (a2 + a3) + dval;
        }
        asm volatile("bar.sync 1, 64;" ::: "memory");

        // A-frag table (352 warp-invariant words):
        //   fw0[d] (d=0..4) at [d*32],  sa = s0(d)
        //   fw1[e] (e=0..5) at [(5+e)*32], sa = s0(e) + 8
        // where s0(x) = 64 - 16x + (l>>2) - 2(l&3); word packs (sa, sa-1).
        // Note fw1[d+1] == old w2(d) since s0(d)-8 == s0(d+1)+8.
        #pragma unroll
        for (int it = 0; it < 6; ++it) {
            int widx = tid + it * 64;
            if (widx < NTAB * 32) {
                int l = widx & 31, dw = widx >> 5;
                int x  = (dw < 5) ? dw : (dw - 5);
                int sa = 64 - 16 * x + (l >> 2) - ((l & 3) << 1) + ((dw < 5) ? 0 : 8);
                float fa = ((unsigned)sa < TAPS) ? sK[sa] : 0.0f;
                float fb = ((unsigned)(sa - 1) < TAPS) ? sK[sa - 1] : 0.0f;
                sTab[widx] = pk_h2(fa, fb);
            }
        }
    } else {
        // ---- warps 2-7: im2col, 8 strips of 576 floats (t in [t0-64, t0+512)) ----
        #pragma unroll
        for (int it = 0; it < 3; ++it) {
            int idx = (tid - 64) + it * 192;             // 0..575, exact
            int b = idx / 72, q8 = idx - b * 72;
            int t = t0 - 64 + q8 * 8;
            float4 v0 = make_float4(0.f, 0.f, 0.f, 0.f);
            float4 v1 = v0;
            if (t >= 0) {
                const float* p = uh + (size_t)b * bstr + t;
                v0 = *reinterpret_cast<const float4*>(p);
                v1 = *reinterpret_cast<const float4*>(p + 4);
            }
            uint4 w;
            w.x = pk_h2(v0.x, v0.y); w.y = pk_h2(v0.z, v0.w);
            w.z = pk_h2(v1.x, v1.y); w.w = pk_h2(v1.z, v1.w);
            *reinterpret_cast<uint4*>(sBuf + b * STRW + q8 * 4) = w;
        }
    }
    __syncthreads();

    // ---- per-warp A fragments: 11 conflict-free LDS.32 ----
    uint32_t fw0[5], fw1[6];
    #pragma unroll
    for (int d = 0; d < 5; ++d) fw0[d] = sTab[d * 32 + lane];
    #pragma unroll
    for (int e = 0; e < 6; ++e) fw1[e] = sTab[(5 + e) * 32 + lane];

    // ---- Banded GEMM: warp (tile = wid>>1, q = wid&1) owns row blocks 4q..4q+3
    //      of one tile; its k-window is k-blocks 4q..4q+7 -> only 4 ldsm.x4 ----
    const int tile = wid >> 1;
    const int q    = wid & 1;
    const uint32_t ldm0 = smem_u32(sBuf) +
        (((lane & 7) * STRW) + tile * 64 + (((lane >> 4) & 1) * 8) +
         (((lane >> 3) & 1) * 4)) * 4;

    float acc[4][4];
    #pragma unroll
    for (int i = 0; i < 4; ++i)
        #pragma unroll
        for (int r = 0; r < 4; ++r) acc[i][r] = 0.0f;

    #pragma unroll
    for (int s = 0; s < 4; ++s) {
        uint32_t b0, b1, b2, b3;                         // kb 2s, kb 2s+1
        ldsm_x4(b0, b1, b2, b3, ldm0 + ((4 * q + 2 * s) * 8) * 4);
        #pragma unroll
        for (int i = 0; i < 4; ++i) {
            const int de = 2 * s - i;                    // uses kb 2s
            const int do_ = 2 * s + 1 - i;               // uses kb 2s+1
            if (de >= 0 && de <= 4)
                mma_f16(acc[i], fw0[de], fw1[de], fw1[de + 1], fw0[de], b0, b1);
            if (do_ >= 0 && do_ <= 4)
                mma_f16(acc[i], fw0[do_], fw1[do_], fw1[do_ + 1], fw0[do_], b2, b3);
        }
    }

    // ---- Direct epilogue: streaming stores (y is write-once) ----
    {
        const int j  = 64 * q + (lane >> 2);             // row within tile; block i adds 16i
        const int nn = (lane & 3) * 2;
        float* p0 = yh + (size_t)nn * bstr + t0 + tile * 128 + j;
        #pragma unroll
        for (int i = 0; i < 4; ++i) {
            float* q0 = p0 + i * 16;
            float* q1 = q0 + bstr;
            __stcs(q0,     acc[i][0]);
            __stcs(q1,     acc[i][1]);
            __stcs(q0 + 8, acc[i][2]);
            __stcs(q1 + 8, acc[i][3]);
        }
    }
}

extern "C" void kernel_launch(void* const* d_in, const int* in_sizes, int n_in,
                              void* d_out, int out_size) {
    const float* u = (const float*)d_in[0];   // (8, 512, 4096)
    const float* B = (const float*)d_in[1];   // (512, 64)
    const float* C = (const float*)d_in[2];   // (1, 512, 64)
    const float* D = (const float*)d_in[3];   // (512,)
    float* y = (float*)d_out;                 // (8, 512, 4096)

    dim3 grid(LSEQ / TCTA, HCH);              // (8, 512) = 4096 CTAs
    conv_mma<<<grid, NT>>>(u, B, C, D, y);
}

// round 16
// speedup vs baseline: 1.0685x; 1.0685x over previous
#include <cuda_runtime.h>
#include <cuda_fp16.h>
#include <cstdint>

#define HCH  512
#define LSEQ 4096
#define TAPS 64

#define NT    256               // 8 warps
#define TCTA  1024              // 8 seq-tiles of 128 per CTA (2 halves of 4)
#define STRW  548               // u32 words per batch strip (544 used + 4 pad), 548%32==4
#define NTAB  11                // deduped A-frag words: fw0[0..4], fw1[0..5]

__device__ __forceinline__ uint32_t pk_h2(float a, float b) {
    __half2 t = __floats2half2_rn(a, b);
    return *reinterpret_cast<uint32_t*>(&t);
}
__device__ __forceinline__ uint32_t smem_u32(const void* p) {
    uint32_t a;
    asm("{ .reg .u64 t; cvta.to.shared.u64 t, %1; cvt.u32.u64 %0, t; }" : "=r"(a) : "l"(p));
    return a;
}
__device__ __forceinline__ void mma_f16(float* d, uint32_t a0, uint32_t a1,
                                        uint32_t a2, uint32_t a3,
                                        uint32_t b0, uint32_t b1) {
    asm volatile(
        "mma.sync.aligned.m16n8k16.row.col.f32.f16.f16.f32 "
        "{%0,%1,%2,%3}, {%4,%5,%6,%7}, {%8,%9}, {%0,%1,%2,%3};"
        : "+f"(d[0]), "+f"(d[1]), "+f"(d[2]), "+f"(d[3])
        : "r"(a0), "r"(a1), "r"(a2), "r"(a3), "r"(b0), "r"(b1));
}
__device__ __forceinline__ void ldsm_x4(uint32_t& r0, uint32_t& r1,
                                        uint32_t& r2, uint32_t& r3, uint32_t addr) {
    asm volatile("ldmatrix.sync.aligned.m8n8.x4.shared.b16 {%0,%1,%2,%3}, [%4];"
                 : "=r"(r0), "=r"(r1), "=r"(r2), "=r"(r3) : "r"(addr));
}

__global__ __launch_bounds__(NT, 5) void conv_mma(const float* __restrict__ up,
                                                  const float* __restrict__ Bp,
                                                  const float* __restrict__ Cp,
                                                  const float* __restrict__ Dp,
                                                  float* __restrict__ yp) {
    __shared__ alignas(16) uint32_t sBuf[8 * STRW];      // 8 fp16 batch strips
    __shared__ alignas(16) float sBC[192];               // B | C | zero pad
    __shared__ float    sK[TAPS];
    __shared__ uint32_t sTab[NTAB * 32];                 // deduped A-frag words

    const int tid  = threadIdx.x;
    const int wid  = tid >> 5;
    const int lane = tid & 31;
    const int h    = blockIdx.y;
    const int t0   = blockIdx.x * TCTA;

    const float* uh = up + (size_t)h * LSEQ;
    float*       yh = yp + (size_t)h * LSEQ;
    const size_t bstr = (size_t)HCH * LSEQ;

    if (tid < 64) {
        // ---- warps 0-1: stage B,C (+zero pad); K correlation; A-frag table ----
        float dval = 0.0f;
        if (tid == 0) dval = Dp[h];
        if (tid < 32) {
            int l = tid & 15;
            const float* src = (tid < 16) ? (Bp + h * TAPS) : (Cp + h * TAPS);
            reinterpret_cast<float4*>(sBC)[(tid < 16 ? 0 : 16) + l] =
                reinterpret_cast<const float4*>(src)[l];
        } else if (tid < 48) {                           // zero pad sBC[128..191]
            reinterpret_cast<float4*>(sBC)[tid] = make_float4(0.f, 0.f, 0.f, 0.f);
        }
        asm volatile("bar.sync 1, 64;" ::: "memory");

        {   // K[s] = sum_j B[j]*C[j+s] (branch-free via pad), K[0] += D[h]
            const int s = tid;
            float a0 = 0.f, a1 = 0.f, a2 = 0.f, a3 = 0.f;
            #pragma unroll
            for (int j = 0; j < TAPS; j += 4) {
                a0 = fmaf(sBC[j],     sBC[64 + j + s],     a0);
                a1 = fmaf(sBC[j + 1], sBC[64 + j + 1 + s], a1);
                a2 = fmaf(sBC[j + 2], sBC[64 + j + 2 + s], a2);
                a3 = fmaf(sBC[j + 3], sBC[64 + j + 3 + s], a3);
            }
            sK[s] = (a0 + a1) + (a2 + a3) + dval;
        }
        asm volatile("bar.sync 1, 64;" ::: "memory");

        // A-frag table (352 warp-invariant words):
        //   fw0[d] d=0..4 at [d*32]  (sa = s0(d)), fw1[e] e=0..5 at [(5+e)*32] (sa = s0(e)+8)
        //   s0(x) = 64 - 16x + (l>>2) - 2(l&3); each word packs (sa, sa-1)
        #pragma unroll
        for (int it = 0; it < 6; ++it) {
            int widx = tid + it * 64;
            if (widx < NTAB * 32) {
                int l = widx & 31, dw = widx >> 5;
                int x  = (dw < 5) ? dw : (dw - 5);
                int sa = 64 - 16 * x + (l >> 2) - ((l & 3) << 1) + ((dw < 5) ? 0 : 8);
                float fa = ((unsigned)sa < TAPS) ? sK[sa] : 0.0f;
                float fb = ((unsigned)(sa - 1) < TAPS) ? sK[sa - 1] : 0.0f;
                sTab[widx] = pk_h2(fa, fb);
            }
        }
    } else {
        // ---- warps 2-7: im2col, 8 strips of 1088 floats (t in [t0-64, t0+1024)) ----
        #pragma unroll
        for (int it = 0; it < 6; ++it) {
            int idx = (tid - 64) + it * 192;             // 8-float group index
            if (idx < 1088) {
                int b = idx / 136, q8 = idx - b * 136;
                int t = t0 - 64 + q8 * 8;
                float4 v0 = make_float4(0.f, 0.f, 0.f, 0.f);
                float4 v1 = v0;
                if (t >= 0) {
                    const float* p = uh + (size_t)b * bstr + t;
                    v0 = *reinterpret_cast<const float4*>(p);
                    v1 = *reinterpret_cast<const float4*>(p + 4);
                }
                uint4 w;
                w.x = pk_h2(v0.x, v0.y); w.y = pk_h2(v0.z, v0.w);
                w.z = pk_h2(v1.x, v1.y); w.w = pk_h2(v1.z, v1.w);
                *reinterpret_cast<uint4*>(sBuf + b * STRW + q8 * 4) = w;
            }
        }
    }
    __syncthreads();

    // ---- per-warp A fragments: 11 conflict-free LDS.32 ----
    uint32_t fw0[5], fw1[6];
    #pragma unroll
    for (int d = 0; d < 5; ++d) fw0[d] = sTab[d * 32 + lane];
    #pragma unroll
    for (int e = 0; e < 6; ++e) fw1[e] = sTab[(5 + e) * 32 + lane];

    // ---- Banded GEMM over two 4-tile halves; warp (tl = wid>>1, q = wid&1)
    //      owns row blocks 4q..4q+3 of tile (tl + 4*half); 4 ldsm.x4 per half ----
    const int tl = wid >> 1;
    const int q  = wid & 1;
    const uint32_t ldm0 = smem_u32(sBuf) +
        (((lane & 7) * STRW) + (((lane >> 4) & 1) * 8) + (((lane >> 3) & 1) * 4)) * 4;
    const int j  = 64 * q + (lane >> 2);
    const int nn = (lane & 3) * 2;

    #pragma unroll 1
    for (int half = 0; half < 2; ++half) {
        const int tile = tl + 4 * half;
        const uint32_t ldmh = ldm0 + (tile * 64) * 4;

        float acc[4][4];
        #pragma unroll
        for (int i = 0; i < 4; ++i)
            #pragma unroll
            for (int r = 0; r < 4; ++r) acc[i][r] = 0.0f;

        #pragma unroll
        for (int s = 0; s < 4; ++s) {
            uint32_t b0, b1, b2, b3;                     // kb 2s, kb 2s+1
            ldsm_x4(b0, b1, b2, b3, ldmh + ((4 * q + 2 * s) * 8) * 4);
            #pragma unroll
            for (int i = 0; i < 4; ++i) {
                const int de  = 2 * s - i;               // uses kb 2s
                const int do_ = 2 * s + 1 - i;           // uses kb 2s+1
                if (de >= 0 && de <= 4)
                    mma_f16(acc[i], fw0[de], fw1[de], fw1[de + 1], fw0[de], b0, b1);
                if (do_ >= 0 && do_ <= 4)
                    mma_f16(acc[i], fw0[do_], fw1[do_], fw1[do_ + 1], fw0[do_], b2, b3);
            }
        }

        // direct epilogue: streaming stores (y is write-once)
        float* p0 = yh + (size_t)nn * bstr + t0 + tile * 128 + j;
        #pragma unroll
        for (int i = 0; i < 4; ++i) {
            float* q0 = p0 + i * 16;
            float* q1 = q0 + bstr;
            __stcs(q0,     acc[i][0]);
            __stcs(q1,     acc[i][1]);
            __stcs(q0 + 8, acc[i][2]);
            __stcs(q1 + 8, acc[i][3]);
        }
    }
}

extern "C" void kernel_launch(void* const* d_in, const int* in_sizes, int n_in,
                              void* d_out, int out_size) {
    const float* u = (const float*)d_in[0];   // (8, 512, 4096)
    const float* B = (const float*)d_in[1];   // (512, 64)
    const float* C = (const float*)d_in[2];   // (1, 512, 64)
    const float* D = (const float*)d_in[3];   // (512,)
    float* y = (float*)d_out;                 // (8, 512, 4096)

    dim3 grid(LSEQ / TCTA, HCH);              // (4, 512) = 2048 CTAs
    conv_mma<<<grid, NT>>>(u, B, C, D, y);
}